// round 5
// baseline (speedup 1.0000x reference)
#include <cuda_runtime.h>

#define BATCH   512
#define SEQ     8192
#define VOCAB   4
#define THREADS 256
#define CHUNKS  (SEQ / THREADS)   // 32 blocks per batch row

// Deterministic reduction scratch (no device allocation allowed).
__device__ float g_partials[BATCH * CHUNKS];

__global__ void __launch_bounds__(THREADS)
evo_main_kernel(const float* __restrict__ f1,
                const float* __restrict__ br1,
                const float* __restrict__ f2,
                const float* __restrict__ br2,
                float* __restrict__ joint)
{
    const int blk   = blockIdx.x;          // 0 .. BATCH*CHUNKS-1
    const int b     = blk / CHUNKS;
    const int chunk = blk % CHUNKS;
    const int m     = chunk * THREADS + threadIdx.x;
    const long idx  = (long)b * SEQ + m;   // site index (float4 granularity)

    // Per-batch scalars (closed-form Jukes-Cantor):
    //   T(t) = q * ones + e * I   with e = exp(-4t/3), q = (1-e)/4
    const float t1 = br1[b];
    const float t2 = br2[b];
    const float e1 = __expf(-1.3333333333333333f * t1);
    const float e2 = __expf(-1.3333333333333333f * t2);
    const float q1 = 0.25f * (1.0f - e1);
    const float q2 = 0.25f * (1.0f - e2);
    // exp(log_prior / SEQ), log_prior = ln(10) - 10*(t1+t2)
    const float scale = __expf((2.302585092994046f - 10.0f * (t1 + t2)) * (1.0f / SEQ));

    const float4 a = ((const float4*)f1)[idx];
    const float4 c = ((const float4*)f2)[idx];

    const float S1 = (a.x + a.y) + (a.z + a.w);
    const float S2 = (c.x + c.y) + (c.z + c.w);
    const float qs1 = q1 * S1;
    const float qs2 = q2 * S2;

    // dot_c = q*S + e*f_c ; joint_c = dot1_c * dot2_c * scale
    float jx = (qs1 + e1 * a.x) * (qs2 + e2 * c.x) * scale;
    float jy = (qs1 + e1 * a.y) * (qs2 + e2 * c.y) * scale;
    float jz = (qs1 + e1 * a.z) * (qs2 + e2 * c.z) * scale;
    float jw = (qs1 + e1 * a.w) * (qs2 + e2 * c.w) * scale;

    ((float4*)joint)[idx] = make_float4(jx, jy, jz, jw);

    // per-site log(0.25 * sum_c joint)
    const float rowsum = 0.25f * ((jx + jy) + (jz + jw));
    float lg = __logf(rowsum);

    // Deterministic block tree-reduce
    __shared__ float sh[THREADS];
    sh[threadIdx.x] = lg;
    __syncthreads();
    #pragma unroll
    for (int s = THREADS / 2; s > 32; s >>= 1) {
        if (threadIdx.x < s) sh[threadIdx.x] += sh[threadIdx.x + s];
        __syncthreads();
    }
    if (threadIdx.x < 32) {
        float v = sh[threadIdx.x] + sh[threadIdx.x + 32];
        #pragma unroll
        for (int off = 16; off > 0; off >>= 1)
            v += __shfl_down_sync(0xFFFFFFFFu, v, off);
        if (threadIdx.x == 0) g_partials[blk] = v;
    }
}

__global__ void evo_reduce_kernel(float* __restrict__ log_p)
{
    const int b = blockIdx.x * blockDim.x + threadIdx.x;
    if (b < BATCH) {
        float s = 0.0f;
        #pragma unroll
        for (int i = 0; i < CHUNKS; i++)
            s += g_partials[b * CHUNKS + i];
        log_p[b] = s;
    }
}

extern "C" void kernel_launch(void* const* d_in, const int* in_sizes, int n_in,
                              void* d_out, int out_size)
{
    const float* f1  = (const float*)d_in[0];   // [512, 8192, 4]
    const float* br1 = (const float*)d_in[1];   // [512]
    const float* f2  = (const float*)d_in[2];   // [512, 8192, 4]
    const float* br2 = (const float*)d_in[3];   // [512]

    float* joint = (float*)d_out;                              // [512, 8192, 4]
    float* log_p = (float*)d_out + (long)BATCH * SEQ * VOCAB;  // [512]

    evo_main_kernel<<<BATCH * CHUNKS, THREADS>>>(f1, br1, f2, br2, joint);
    evo_reduce_kernel<<<(BATCH + 127) / 128, 128>>>(log_p);
}

// round 6
// speedup vs baseline: 1.0189x; 1.0189x over previous
#include <cuda_runtime.h>

#define BATCH   512
#define SEQ     8192
#define VOCAB   4
#define THREADS 256
#define CHUNKS  (SEQ / THREADS)   // 32 blocks per batch row

// Deterministic reduction scratch (no device allocation allowed).
__device__ float g_partials[BATCH * CHUNKS];

__global__ void __launch_bounds__(THREADS)
evo_main_kernel(const float* __restrict__ f1,
                const float* __restrict__ br1,
                const float* __restrict__ f2,
                const float* __restrict__ br2,
                float* __restrict__ joint)
{
    const int blk   = blockIdx.x;          // 0 .. BATCH*CHUNKS-1
    const int b     = blk / CHUNKS;
    const int chunk = blk % CHUNKS;
    const int m     = chunk * THREADS + threadIdx.x;
    const long idx  = (long)b * SEQ + m;   // site index (float4 granularity)

    // Per-batch scalars (closed-form Jukes-Cantor):
    //   T(t) = q * ones + e * I   with e = exp(-4t/3), q = (1-e)/4
    const float t1 = br1[b];
    const float t2 = br2[b];
    const float e1 = __expf(-1.3333333333333333f * t1);
    const float e2 = __expf(-1.3333333333333333f * t2);
    const float q1 = 0.25f * (1.0f - e1);
    const float q2 = 0.25f * (1.0f - e2);
    // exp(log_prior / SEQ), log_prior = ln(10) - 10*(t1+t2)
    const float scale = __expf((2.302585092994046f - 10.0f * (t1 + t2)) * (1.0f / SEQ));

    const float4 a = ((const float4*)f1)[idx];
    const float4 c = ((const float4*)f2)[idx];

    const float S1 = (a.x + a.y) + (a.z + a.w);
    const float S2 = (c.x + c.y) + (c.z + c.w);
    const float qs1 = q1 * S1;
    const float qs2 = q2 * S2;

    // dot_c = q*S + e*f_c ; joint_c = dot1_c * dot2_c * scale
    float jx = (qs1 + e1 * a.x) * (qs2 + e2 * c.x) * scale;
    float jy = (qs1 + e1 * a.y) * (qs2 + e2 * c.y) * scale;
    float jz = (qs1 + e1 * a.z) * (qs2 + e2 * c.z) * scale;
    float jw = (qs1 + e1 * a.w) * (qs2 + e2 * c.w) * scale;

    ((float4*)joint)[idx] = make_float4(jx, jy, jz, jw);

    // per-site log(0.25 * sum_c joint)
    const float rowsum = 0.25f * ((jx + jy) + (jz + jw));
    float lg = __logf(rowsum);

    // Deterministic block tree-reduce
    __shared__ float sh[THREADS];
    sh[threadIdx.x] = lg;
    __syncthreads();
    #pragma unroll
    for (int s = THREADS / 2; s > 32; s >>= 1) {
        if (threadIdx.x < s) sh[threadIdx.x] += sh[threadIdx.x + s];
        __syncthreads();
    }
    if (threadIdx.x < 32) {
        float v = sh[threadIdx.x] + sh[threadIdx.x + 32];
        #pragma unroll
        for (int off = 16; off > 0; off >>= 1)
            v += __shfl_down_sync(0xFFFFFFFFu, v, off);
        if (threadIdx.x == 0) g_partials[blk] = v;
    }
}

__global__ void evo_reduce_kernel(float* __restrict__ log_p)
{
    const int b = blockIdx.x * blockDim.x + threadIdx.x;
    if (b < BATCH) {
        float s = 0.0f;
        #pragma unroll
        for (int i = 0; i < CHUNKS; i++)
            s += g_partials[b * CHUNKS + i];
        log_p[b] = s;
    }
}

extern "C" void kernel_launch(void* const* d_in, const int* in_sizes, int n_in,
                              void* d_out, int out_size)
{
    const float* f1  = (const float*)d_in[0];   // [512, 8192, 4]
    const float* br1 = (const float*)d_in[1];   // [512]
    const float* f2  = (const float*)d_in[2];   // [512, 8192, 4]
    const float* br2 = (const float*)d_in[3];   // [512]

    float* joint = (float*)d_out;                              // [512, 8192, 4]
    float* log_p = (float*)d_out + (long)BATCH * SEQ * VOCAB;  // [512]

    evo_main_kernel<<<BATCH * CHUNKS, THREADS>>>(f1, br1, f2, br2, joint);
    evo_reduce_kernel<<<(BATCH + 127) / 128, 128>>>(log_p);
}